// round 10
// baseline (speedup 1.0000x reference)
#include <cuda_runtime.h>
#include <math.h>
#include <stdint.h>

#define NG   8192
#define SS   64
#define DD   128
#define HH   256
#define KK   8
#define GPB  24                      // groups per batch (24 producer warps)
#define NBATCH ((NG + GPB - 1) / GPB)   // 342 (last batch partial: 8 groups)
#define GRID_B 152                   // 1 block per SM
#define NT   1024
#define EPSV 0.01f

#define OFF_MIX   (NG * DD)
#define OFF_SCALE (OFF_MIX + NG * KK)
#define OFF_ALPHA (OFF_SCALE + NG)
#define OFF_BETA  (OFF_ALPHA + NG)

// dynamic smem layout (bytes)
#define SM_REP   0                    // double2[2][12][64] = 24576
#define SM_H     24576                // float[24][257]     = 24672
#define SM_W2T   49248                // float[10][256]     = 10240
#define SM_TOTAL 59488

// named barriers: 1,2 = rep EMPTY[p], 3,4 = rep FULL[p], 5 = consumer-local
#define BAR_EMPTY(p) (1 + (p))
#define BAR_FULL(p)  (3 + (p))
#define BAR_CONS     5

__device__ __forceinline__ void bar_sync(int id, int cnt) {
    asm volatile("bar.sync %0, %1;" :: "r"(id), "r"(cnt) : "memory");
}
__device__ __forceinline__ void bar_arrive(int id, int cnt) {
    asm volatile("bar.arrive %0, %1;" :: "r"(id), "r"(cnt) : "memory");
}

// ---- packed f32x2 helpers (sm_103a) ----------------------------------------
__device__ __forceinline__ double add2(double a, double b) {
    double r; asm("add.rn.f32x2 %0,%1,%2;" : "=d"(r) : "d"(a), "d"(b)); return r;
}
__device__ __forceinline__ double fma2(double a, double b, double c) {
    double r; asm("fma.rn.f32x2 %0,%1,%2,%3;" : "=d"(r) : "d"(a), "d"(b), "d"(c)); return r;
}
__device__ __forceinline__ double pack2(float lo, float hi) {
    double r; asm("mov.b64 %0,{%1,%2};" : "=d"(r) : "f"(lo), "f"(hi)); return r;
}
__device__ __forceinline__ float2 unpack2(double v) {
    float2 r; asm("mov.b64 {%0,%1},%2;" : "=f"(r.x), "=f"(r.y) : "d"(v)); return r;
}
__device__ __forceinline__ float softplus_f(float v) {
    return v > 20.0f ? v : log1pf(expf(v));
}

__global__ __launch_bounds__(NT, 1)
void wide_pipeline_kernel(
    const float* __restrict__ x,
    const float* __restrict__ y,
    const float* __restrict__ anchor_x,
    const float* __restrict__ anchor_y,
    const float* __restrict__ W1,
    const float* __restrict__ b1,
    const float* __restrict__ W2,
    const float* __restrict__ b2,
    float* __restrict__ out)
{
    extern __shared__ char smem[];
    double2 (*rep_buf)[GPB / 2][DD / 2] =
        (double2(*)[GPB / 2][DD / 2])(smem + SM_REP);    // [2][12][64]
    float (*h_s)[HH + 1] = (float(*)[HH + 1])(smem + SM_H);   // [24][257]
    float (*w2t)[HH]     = (float(*)[HH])(smem + SM_W2T);     // [10][256]

    const int tid = threadIdx.x;
    const int wid = tid >> 5;
    const int l   = tid & 31;
    const bool producer = (wid < GPB);

    if (!producer) {
        // consumers (256 threads) stage transposed W2; ordered by first BAR_CONS
        for (int i = tid - GPB * 32; i < HH * (KK + 2); i += 256) {
            int j = i / (KK + 2);
            int k = i - j * (KK + 2);
            w2t[k][j] = W2[i];
        }
    }
    __syncthreads();

    int ib = 0;
    for (int B = blockIdx.x; B < NBATCH; B += GRID_B, ++ib) {
        const int p = ib & 1;

        if (producer) {
            // ================= PRODUCER warp (group w of batch B) ==============
            const int w = wid;
            const int g = B * GPB + w;
            const bool valid = (g < NG);

            float4 rep = make_float4(0.f, 0.f, 0.f, 0.f);
            if (valid) {
                const float4* xg =
                    reinterpret_cast<const float4*>(x + (size_t)g * SS * DD) + l;
                const float* yg = y + (size_t)g * SS;
                float4 a4 =
                    reinterpret_cast<const float4*>(anchor_x + (size_t)g * DD)[l];
                const float ayv = anchor_y[g];

                const double na_lo = pack2(-a4.x, -a4.y);
                const double na_hi = pack2(-a4.z, -a4.w);

                double sx_lo = 0.0, sx_hi = 0.0;
                double sxy_lo = 0.0, sxy_hi = 0.0;
                double sxx2 = 0.0;
                float  sy = 0.f;

                float4 c0, c1, c2, c3;
                float  yv0, yv1, yv2, yv3;
                c0 = xg[0 * (DD / 4)]; c1 = xg[1 * (DD / 4)];
                c2 = xg[2 * (DD / 4)]; c3 = xg[3 * (DD / 4)];
                yv0 = yg[0]; yv1 = yg[1]; yv2 = yg[2]; yv3 = yg[3];

                #pragma unroll
                for (int b = 0; b < SS / 4; ++b) {
                    float4 n0, n1, n2, n3;
                    float  yn0, yn1, yn2, yn3;
                    if (b < SS / 4 - 1) {
                        const int base = (b + 1) * 4;
                        n0 = xg[(base + 0) * (DD / 4)];
                        n1 = xg[(base + 1) * (DD / 4)];
                        n2 = xg[(base + 2) * (DD / 4)];
                        n3 = xg[(base + 3) * (DD / 4)];
                        yn0 = yg[base + 0]; yn1 = yg[base + 1];
                        yn2 = yg[base + 2]; yn3 = yg[base + 3];
                    }
                    {
                        float4 cc[4] = {c0, c1, c2, c3};
                        float  yy[4] = {yv0, yv1, yv2, yv3};
                        #pragma unroll
                        for (int k = 0; k < 4; ++k) {
                            double2 xd = *reinterpret_cast<double2*>(&cc[k]);
                            float yr = yy[k] - ayv;
                            double yr2 = pack2(yr, yr);
                            double xr_lo = add2(xd.x, na_lo);
                            double xr_hi = add2(xd.y, na_hi);
                            sx_lo  = add2(sx_lo, xr_lo);
                            sx_hi  = add2(sx_hi, xr_hi);
                            sxy_lo = fma2(xr_lo, yr2, sxy_lo);
                            sxy_hi = fma2(xr_hi, yr2, sxy_hi);
                            sxx2   = fma2(xr_lo, xr_lo, sxx2);
                            sxx2   = fma2(xr_hi, xr_hi, sxx2);
                            sy += yr;
                        }
                    }
                    c0 = n0; c1 = n1; c2 = n2; c3 = n3;
                    yv0 = yn0; yv1 = yn1; yv2 = yn2; yv3 = yn3;
                }

                float2 sxxp = unpack2(sxx2);
                float sxx = sxxp.x + sxxp.y;
                float2 sxl = unpack2(sx_lo),  sxh = unpack2(sx_hi);
                float2 syl = unpack2(sxy_lo), syh = unpack2(sxy_hi);
                float tot = sxl.x + sxl.y + sxh.x + sxh.y;

                #pragma unroll
                for (int o = 16; o > 0; o >>= 1) {
                    sxx += __shfl_xor_sync(0xFFFFFFFFu, sxx, o);
                    tot += __shfl_xor_sync(0xFFFFFFFFu, tot, o);
                }

                const float nD      = (float)(SS * DD);
                const float var     = (sxx - tot * tot / nD) / (nD - 1.0f);
                const float inv_var = 1.0f / var;
                const float c       = sy / (float)SS;
                const float inv_nm1 = 1.0f / (float)(SS - 1);

                rep.x = (syl.x - sxl.x * c) * inv_nm1 * inv_var;
                rep.y = (syl.y - sxl.y * c) * inv_nm1 * inv_var;
                rep.z = (syh.x - sxh.x * c) * inv_nm1 * inv_var;
                rep.w = (syh.y - sxh.y * c) * inv_nm1 * inv_var;

                reinterpret_cast<float4*>(out + (size_t)g * DD)[l] = rep;
            }

            if (ib >= 2) bar_sync(BAR_EMPTY(p), NT);

            {
                const int pp  = w >> 1;
                const int sel = w & 1;
                float* base = reinterpret_cast<float*>(&rep_buf[p][pp][0]);
                base[2 * (4 * l + 0) + sel] = rep.x;
                base[2 * (4 * l + 1) + sel] = rep.y;
                base[2 * (4 * l + 2) + sel] = rep.z;
                base[2 * (4 * l + 3) + sel] = rep.w;
            }
            asm volatile("membar.cta;" ::: "memory");
            bar_arrive(BAR_FULL(p), NT);
        } else {
            // ================= CONSUMERS (warps 24..31, 256 threads) ===========
            bar_sync(BAR_FULL(p), NT);

            const int j = tid - GPB * 32;       // 0..255 hidden unit
            {
                const float bj = b1[j];
                // two passes of 6 group-pairs; W1 re-read is L1-hot
                #pragma unroll
                for (int pass = 0; pass < 2; ++pass) {
                    double acc[6];
                    #pragma unroll
                    for (int pp = 0; pp < 6; ++pp) acc[pp] = pack2(bj, bj);

                    #pragma unroll 4
                    for (int d = 0; d < DD; d += 2) {
                        float w0  = W1[(d + 0) * HH + j];
                        float w1v = W1[(d + 1) * HH + j];
                        double wd0 = pack2(w0, w0);
                        double wd1 = pack2(w1v, w1v);
                        #pragma unroll
                        for (int pp = 0; pp < 6; ++pp) {
                            double2 rp = rep_buf[p][pass * 6 + pp][d >> 1];
                            acc[pp] = fma2(rp.x, wd0, acc[pp]);
                            acc[pp] = fma2(rp.y, wd1, acc[pp]);
                        }
                    }
                    #pragma unroll
                    for (int pp = 0; pp < 6; ++pp) {
                        float2 hv = unpack2(acc[pp]);
                        h_s[2 * (pass * 6 + pp) + 0][j] = tanhf(hv.x);
                        h_s[2 * (pass * 6 + pp) + 1][j] = tanhf(hv.y);
                    }
                }
            }
            bar_sync(BAR_CONS, 256);            // h_s complete; rep reads drained
            bar_arrive(BAR_EMPTY(p), NT);       // release rep buffer p

            // layer 2 + heads: each consumer warp handles 3 groups
            {
                const int cw = wid - GPB;       // 0..7
                #pragma unroll
                for (int gi = 0; gi < 3; ++gi) {
                    const int wg = 3 * cw + gi;         // 0..23
                    const int gl = B * GPB + wg;

                    float acc[KK + 2];
                    #pragma unroll
                    for (int k = 0; k < KK + 2; ++k) acc[k] = 0.f;

                    #pragma unroll
                    for (int t = 0; t < HH / 32; ++t) {
                        const int jj = 32 * t + l;
                        const float hv = h_s[wg][jj];
                        #pragma unroll
                        for (int k = 0; k < KK + 2; ++k)
                            acc[k] = fmaf(hv, w2t[k][jj], acc[k]);
                    }
                    #pragma unroll
                    for (int k = 0; k < KK + 2; ++k) {
                        #pragma unroll
                        for (int o = 16; o > 0; o >>= 1)
                            acc[k] += __shfl_xor_sync(0xFFFFFFFFu, acc[k], o);
                    }

                    if (l == 0 && gl < NG) {
                        float o0 = acc[0] + b2[0];
                        float o1 = acc[1] + b2[1];
                        float alpha = softplus_f(o0) * (1.0f - EPSV) + EPSV;
                        float beta  = softplus_f(o1) * (1.0f - EPSV) + EPSV;

                        float ok[KK];
                        float m = -INFINITY;
                        #pragma unroll
                        for (int k = 0; k < KK; ++k) {
                            ok[k] = acc[2 + k] + b2[2 + k];
                            m = fmaxf(m, ok[k]);
                        }
                        float s = 0.f;
                        #pragma unroll
                        for (int k = 0; k < KK; ++k) { ok[k] = expf(ok[k] - m); s += ok[k]; }
                        float inv = 1.0f / s;
                        #pragma unroll
                        for (int k = 0; k < KK; ++k)
                            out[OFF_MIX + (size_t)gl * KK + k] = ok[k] * inv;

                        out[OFF_SCALE + gl] = sqrtf(beta / alpha);
                        out[OFF_ALPHA + gl] = alpha;
                        out[OFF_BETA  + gl] = beta;
                    }
                }
            }
        }
    }
}

extern "C" void kernel_launch(void* const* d_in, const int* in_sizes, int n_in,
                              void* d_out, int out_size) {
    // inputs (metadata order): index, x, y, anchor_x, anchor_y, W1, b1, W2, b2
    const float* x        = (const float*)d_in[1];
    const float* y        = (const float*)d_in[2];
    const float* anchor_x = (const float*)d_in[3];
    const float* anchor_y = (const float*)d_in[4];
    const float* W1       = (const float*)d_in[5];
    const float* b1       = (const float*)d_in[6];
    const float* W2       = (const float*)d_in[7];
    const float* b2       = (const float*)d_in[8];
    float* out            = (float*)d_out;

    static bool attr_set = false;
    if (!attr_set) {
        cudaFuncSetAttribute(wide_pipeline_kernel,
                             cudaFuncAttributeMaxDynamicSharedMemorySize, SM_TOTAL);
        attr_set = true;
    }
    wide_pipeline_kernel<<<GRID_B, NT, SM_TOTAL>>>(x, y, anchor_x, anchor_y,
                                                   W1, b1, W2, b2, out);
}

// round 11
// speedup vs baseline: 1.0258x; 1.0258x over previous
#include <cuda_runtime.h>
#include <math.h>
#include <stdint.h>

#define NG   8192
#define SS   64
#define DD   128
#define HH   256
#define KK   8
#define GPB  8
#define NBATCH (NG / GPB)           // 1024
#define GRID_B 456                  // 3 blocks/SM on 152 SMs
#define NT   384
#define EPSV 0.01f

#define OFF_MIX   (NG * DD)
#define OFF_SCALE (OFF_MIX + NG * KK)
#define OFF_ALPHA (OFF_SCALE + NG)
#define OFF_BETA  (OFF_ALPHA + NG)

// named barriers: 1,2 = rep EMPTY[pb], 3,4 = rep FULL[pb], 5 = consumer-local
#define BAR_EMPTY(pb) (1 + (pb))
#define BAR_FULL(pb)  (3 + (pb))
#define BAR_CONS      5

__device__ __forceinline__ void bar_sync(int id, int cnt) {
    asm volatile("bar.sync %0, %1;" :: "r"(id), "r"(cnt) : "memory");
}
__device__ __forceinline__ void bar_arrive(int id, int cnt) {
    asm volatile("bar.arrive %0, %1;" :: "r"(id), "r"(cnt) : "memory");
}

// ---- packed f32x2 helpers (sm_103a) ----------------------------------------
__device__ __forceinline__ double add2(double a, double b) {
    double r; asm("add.rn.f32x2 %0,%1,%2;" : "=d"(r) : "d"(a), "d"(b)); return r;
}
__device__ __forceinline__ double fma2(double a, double b, double c) {
    double r; asm("fma.rn.f32x2 %0,%1,%2,%3;" : "=d"(r) : "d"(a), "d"(b), "d"(c)); return r;
}
__device__ __forceinline__ double pack2(float lo, float hi) {
    double r; asm("mov.b64 %0,{%1,%2};" : "=d"(r) : "f"(lo), "f"(hi)); return r;
}
__device__ __forceinline__ float2 unpack2(double v) {
    float2 r; asm("mov.b64 {%0,%1},%2;" : "=f"(r.x), "=f"(r.y) : "d"(v)); return r;
}
__device__ __forceinline__ float softplus_f(float v) {
    return v > 20.0f ? v : log1pf(expf(v));
}

__global__ __launch_bounds__(NT, 3)
void pipeline3_kernel(
    const float* __restrict__ x,
    const float* __restrict__ y,
    const float* __restrict__ anchor_x,
    const float* __restrict__ anchor_y,
    const float* __restrict__ W1,
    const float* __restrict__ b1,
    const float* __restrict__ W2,
    const float* __restrict__ b2,
    float* __restrict__ out)
{
    __shared__ double2 rep_buf[2][GPB / 2][DD / 2];   // 8 KB
    __shared__ float   h_s[GPB][HH + 1];              // 8.2 KB
    __shared__ float   w2t[KK + 2][HH];               // 10 KB

    const int tid = threadIdx.x;
    const int wid = tid >> 5;
    const int l   = tid & 31;
    const bool producer = (wid < 8);

    if (!producer) {
        // consumers (128 threads) stage transposed W2; ordered by first use
        for (int i = tid - 256; i < HH * (KK + 2); i += 128) {
            int j = i / (KK + 2);
            int k = i - j * (KK + 2);
            w2t[k][j] = W2[i];
        }
    }
    __syncthreads();

    int ib = 0;
    for (int B = blockIdx.x; B < NBATCH; B += GRID_B, ++ib) {
        const int pb = ib & 1;

        if (producer) {
            // ================= PRODUCER warp (group w of batch B) ==============
            const int w = wid;
            const int g = B * GPB + w;

            const float4* xg = reinterpret_cast<const float4*>(x + (size_t)g * SS * DD) + l;
            float4 a4 = reinterpret_cast<const float4*>(anchor_x + (size_t)g * DD)[l];
            const float ayv = anchor_y[g];
            const float* yg = y + (size_t)g * SS;
            const float ya = yg[l]      - ayv;   // rows 0..31 (lane-indexed)
            const float yb = yg[32 + l] - ayv;   // rows 32..63

            const double na_lo = pack2(-a4.x, -a4.y);
            const double na_hi = pack2(-a4.z, -a4.w);

            double sx_lo = 0.0, sx_hi = 0.0;
            double sxy_lo = 0.0, sxy_hi = 0.0;
            double sxx2 = 0.0;
            float  sy = 0.f;

            float4 c0, c1, c2, c3;
            c0 = xg[0 * (DD / 4)]; c1 = xg[1 * (DD / 4)];
            c2 = xg[2 * (DD / 4)]; c3 = xg[3 * (DD / 4)];

            #pragma unroll
            for (int b = 0; b < SS / 4; ++b) {
                float4 n0, n1, n2, n3;
                if (b < SS / 4 - 1) {
                    const int base = (b + 1) * 4;
                    n0 = xg[(base + 0) * (DD / 4)];
                    n1 = xg[(base + 1) * (DD / 4)];
                    n2 = xg[(base + 2) * (DD / 4)];
                    n3 = xg[(base + 3) * (DD / 4)];
                }
                {
                    float4 cc[4] = {c0, c1, c2, c3};
                    const float ysel = (b < 8) ? ya : yb;
                    #pragma unroll
                    for (int k = 0; k < 4; ++k) {
                        double2 xd = *reinterpret_cast<double2*>(&cc[k]);
                        float yr = __shfl_sync(0xFFFFFFFFu, ysel, (4 * b + k) & 31);
                        double yr2 = pack2(yr, yr);
                        double xr_lo = add2(xd.x, na_lo);
                        double xr_hi = add2(xd.y, na_hi);
                        sx_lo  = add2(sx_lo, xr_lo);
                        sx_hi  = add2(sx_hi, xr_hi);
                        sxy_lo = fma2(xr_lo, yr2, sxy_lo);
                        sxy_hi = fma2(xr_hi, yr2, sxy_hi);
                        sxx2   = fma2(xr_lo, xr_lo, sxx2);
                        sxx2   = fma2(xr_hi, xr_hi, sxx2);
                        sy += yr;
                    }
                }
                c0 = n0; c1 = n1; c2 = n2; c3 = n3;
            }

            float2 sxxp = unpack2(sxx2);
            float sxx = sxxp.x + sxxp.y;
            float2 sxl = unpack2(sx_lo),  sxh = unpack2(sx_hi);
            float2 syl = unpack2(sxy_lo), syh = unpack2(sxy_hi);
            float tot = sxl.x + sxl.y + sxh.x + sxh.y;

            #pragma unroll
            for (int o = 16; o > 0; o >>= 1) {
                sxx += __shfl_xor_sync(0xFFFFFFFFu, sxx, o);
                tot += __shfl_xor_sync(0xFFFFFFFFu, tot, o);
            }

            const float nD      = (float)(SS * DD);
            const float var     = (sxx - tot * tot / nD) / (nD - 1.0f);
            const float inv_var = 1.0f / var;
            const float c       = sy / (float)SS;
            const float inv_nm1 = 1.0f / (float)(SS - 1);

            float4 rep;
            rep.x = (syl.x - sxl.x * c) * inv_nm1 * inv_var;
            rep.y = (syl.y - sxl.y * c) * inv_nm1 * inv_var;
            rep.z = (syh.x - sxh.x * c) * inv_nm1 * inv_var;
            rep.w = (syh.y - sxh.y * c) * inv_nm1 * inv_var;

            reinterpret_cast<float4*>(out + (size_t)g * DD)[l] = rep;

            if (ib >= 2) bar_sync(BAR_EMPTY(pb), NT);

            {
                const int pp  = w >> 1;
                const int sel = w & 1;
                float* base = reinterpret_cast<float*>(&rep_buf[pb][pp][0]);
                base[2 * (4 * l + 0) + sel] = rep.x;
                base[2 * (4 * l + 1) + sel] = rep.y;
                base[2 * (4 * l + 2) + sel] = rep.z;
                base[2 * (4 * l + 3) + sel] = rep.w;
            }
            asm volatile("membar.cta;" ::: "memory");
            bar_arrive(BAR_FULL(pb), NT);
        } else {
            // ================= CONSUMERS (warps 8..11, 128 threads) ============
            bar_sync(BAR_FULL(pb), NT);

            const int ct = tid - 256;            // 0..127
            // layer 1 in two register-lean passes: j = ct, then j = ct + 128
            #pragma unroll
            for (int pass = 0; pass < 2; ++pass) {
                const int j = ct + 128 * pass;
                const float bj = b1[j];
                double acc[GPB / 2];
                #pragma unroll
                for (int pp = 0; pp < GPB / 2; ++pp) acc[pp] = pack2(bj, bj);

                #pragma unroll 4
                for (int d = 0; d < DD; d += 2) {
                    float w0  = W1[(d + 0) * HH + j];
                    float w1v = W1[(d + 1) * HH + j];
                    double wd0 = pack2(w0, w0);
                    double wd1 = pack2(w1v, w1v);
                    #pragma unroll
                    for (int pp = 0; pp < GPB / 2; ++pp) {
                        double2 rp = rep_buf[pb][pp][d >> 1];
                        acc[pp] = fma2(rp.x, wd0, acc[pp]);
                        acc[pp] = fma2(rp.y, wd1, acc[pp]);
                    }
                }
                #pragma unroll
                for (int pp = 0; pp < GPB / 2; ++pp) {
                    float2 hv = unpack2(acc[pp]);
                    h_s[2 * pp + 0][j] = tanhf(hv.x);
                    h_s[2 * pp + 1][j] = tanhf(hv.y);
                }
            }
            bar_sync(BAR_CONS, 128);             // h_s complete; rep reads drained
            bar_arrive(BAR_EMPTY(pb), NT);       // release rep buffer

            // layer 2 + heads: each consumer warp handles 2 groups
            {
                const int cw = wid - 8;          // 0..3
                float acc[2][KK + 2];
                #pragma unroll
                for (int gi = 0; gi < 2; ++gi)
                    #pragma unroll
                    for (int k = 0; k < KK + 2; ++k) acc[gi][k] = 0.f;

                #pragma unroll
                for (int t = 0; t < HH / 32; ++t) {
                    const int j = 32 * t + l;
                    const float h0 = h_s[2 * cw + 0][j];
                    const float h1 = h_s[2 * cw + 1][j];
                    #pragma unroll
                    for (int k = 0; k < KK + 2; ++k) {
                        const float wv = w2t[k][j];
                        acc[0][k] = fmaf(h0, wv, acc[0][k]);
                        acc[1][k] = fmaf(h1, wv, acc[1][k]);
                    }
                }
                #pragma unroll
                for (int gi = 0; gi < 2; ++gi)
                    #pragma unroll
                    for (int k = 0; k < KK + 2; ++k)
                        #pragma unroll
                        for (int o = 16; o > 0; o >>= 1)
                            acc[gi][k] += __shfl_xor_sync(0xFFFFFFFFu, acc[gi][k], o);

                if (l == 0) {
                    #pragma unroll
                    for (int gi = 0; gi < 2; ++gi) {
                        const int gl = B * GPB + 2 * cw + gi;
                        float o0 = acc[gi][0] + b2[0];
                        float o1 = acc[gi][1] + b2[1];
                        float alpha = softplus_f(o0) * (1.0f - EPSV) + EPSV;
                        float beta  = softplus_f(o1) * (1.0f - EPSV) + EPSV;

                        float ok[KK];
                        float m = -INFINITY;
                        #pragma unroll
                        for (int k = 0; k < KK; ++k) {
                            ok[k] = acc[gi][2 + k] + b2[2 + k];
                            m = fmaxf(m, ok[k]);
                        }
                        float s = 0.f;
                        #pragma unroll
                        for (int k = 0; k < KK; ++k) { ok[k] = expf(ok[k] - m); s += ok[k]; }
                        float inv = 1.0f / s;
                        #pragma unroll
                        for (int k = 0; k < KK; ++k)
                            out[OFF_MIX + (size_t)gl * KK + k] = ok[k] * inv;

                        out[OFF_SCALE + gl] = sqrtf(beta / alpha);
                        out[OFF_ALPHA + gl] = alpha;
                        out[OFF_BETA  + gl] = beta;
                    }
                }
            }
        }
    }
}

extern "C" void kernel_launch(void* const* d_in, const int* in_sizes, int n_in,
                              void* d_out, int out_size) {
    // inputs (metadata order): index, x, y, anchor_x, anchor_y, W1, b1, W2, b2
    const float* x        = (const float*)d_in[1];
    const float* y        = (const float*)d_in[2];
    const float* anchor_x = (const float*)d_in[3];
    const float* anchor_y = (const float*)d_in[4];
    const float* W1       = (const float*)d_in[5];
    const float* b1       = (const float*)d_in[6];
    const float* W2       = (const float*)d_in[7];
    const float* b2       = (const float*)d_in[8];
    float* out            = (float*)d_out;

    pipeline3_kernel<<<GRID_B, NT>>>(x, y, anchor_x, anchor_y,
                                     W1, b1, W2, b2, out);
}

// round 12
// speedup vs baseline: 1.4077x; 1.3723x over previous
#include <cuda_runtime.h>
#include <math.h>

#define NG   8192
#define SS   64
#define DD   128
#define HH   256
#define KK   8
#define GPB  8
#define NBATCH (NG / GPB)          // 1024
#define GRID   296                 // 2 blocks per SM
#define EPSV 0.01f

#define OFF_MIX   (NG * DD)
#define OFF_SCALE (OFF_MIX + NG * KK)
#define OFF_ALPHA (OFF_SCALE + NG)
#define OFF_BETA  (OFF_ALPHA + NG)

// named barrier ids: 1,2 = EMPTY[p], 3,4 = FULL[p], 5 = consumer-local
#define BAR_EMPTY(p) (1 + (p))
#define BAR_FULL(p)  (3 + (p))
#define BAR_CONS     5

// prefetch distance in 4-row batches (~6 batches x ~90cyc = ~540cyc of lead)
#define PFD 6

__device__ __forceinline__ void bar_sync(int id, int cnt) {
    asm volatile("bar.sync %0, %1;" :: "r"(id), "r"(cnt) : "memory");
}
__device__ __forceinline__ void bar_arrive(int id, int cnt) {
    asm volatile("bar.arrive %0, %1;" :: "r"(id), "r"(cnt) : "memory");
}
__device__ __forceinline__ void prefetch_l2(const void* p) {
    asm volatile("prefetch.global.L2 [%0];" :: "l"(p));
}

// ---- packed f32x2 helpers (sm_103a) ----------------------------------------
__device__ __forceinline__ double add2(double a, double b) {
    double r; asm("add.rn.f32x2 %0,%1,%2;" : "=d"(r) : "d"(a), "d"(b)); return r;
}
__device__ __forceinline__ double fma2(double a, double b, double c) {
    double r; asm("fma.rn.f32x2 %0,%1,%2,%3;" : "=d"(r) : "d"(a), "d"(b), "d"(c)); return r;
}
__device__ __forceinline__ double pack2(float lo, float hi) {
    double r; asm("mov.b64 %0,{%1,%2};" : "=d"(r) : "f"(lo), "f"(hi)); return r;
}
__device__ __forceinline__ float2 unpack2(double v) {
    float2 r; asm("mov.b64 {%0,%1},%2;" : "=f"(r.x), "=f"(r.y) : "d"(v)); return r;
}
__device__ __forceinline__ float softplus_f(float v) {
    return v > 20.0f ? v : log1pf(expf(v));
}

__global__ __launch_bounds__(512, 2)
void pipeline_kernel(
    const float* __restrict__ x,
    const float* __restrict__ y,
    const float* __restrict__ anchor_x,
    const float* __restrict__ anchor_y,
    const float* __restrict__ W1,
    const float* __restrict__ b1,
    const float* __restrict__ W2,
    const float* __restrict__ b2,
    float* __restrict__ out)
{
    __shared__ double2 rep_buf[2][GPB / 2][DD / 2];  // double-buffered rep, 8 KB
    __shared__ float   h_s[GPB][HH + 1];             // 8.2 KB (consumer-private)
    __shared__ float   w2t[KK + 2][HH];              // 10 KB

    const int tid = threadIdx.x;
    const int wid = tid >> 5;
    const int l   = tid & 31;
    const bool producer = (wid < 8);

    if (!producer) {
        // consumers stage transposed W2 once (ordered by first BAR_CONS sync)
        for (int i = tid - 256; i < HH * (KK + 2); i += 256) {
            int j = i / (KK + 2);
            int k = i - j * (KK + 2);
            w2t[k][j] = W2[i];
        }
    }

    int ib = 0;
    for (int B = blockIdx.x; B < NBATCH; B += GRID, ++ib) {
        const int p = ib & 1;

        if (producer) {
            // ================= PRODUCER: stats for group g =====================
            const int w = wid;
            const int g = B * GPB + w;

            const float4* xg = reinterpret_cast<const float4*>(x + (size_t)g * SS * DD) + l;
            const float*  yg = y + (size_t)g * SS;
            float4 a4 = reinterpret_cast<const float4*>(anchor_x + (size_t)g * DD)[l];
            const float ayv = anchor_y[g];

            const double na_lo = pack2(-a4.x, -a4.y);
            const double na_hi = pack2(-a4.z, -a4.w);

            double sx_lo = 0.0, sx_hi = 0.0;
            double sxy_lo = 0.0, sxy_hi = 0.0;
            double sxx2 = 0.0;
            float  sy = 0.f;

            // prologue: L2-prefetch batches 2..PFD+1 (batches 0/1 load below)
            #pragma unroll
            for (int s = 2; s < PFD + 2 && s < SS / 4; ++s) {
                #pragma unroll
                for (int r = 0; r < 4; ++r)
                    prefetch_l2(xg + (4 * s + r) * (DD / 4));
            }

            float4 c0, c1, c2, c3;
            float  yv0, yv1, yv2, yv3;
            c0 = xg[0 * (DD / 4)]; c1 = xg[1 * (DD / 4)];
            c2 = xg[2 * (DD / 4)]; c3 = xg[3 * (DD / 4)];
            yv0 = yg[0]; yv1 = yg[1]; yv2 = yg[2]; yv3 = yg[3];

            #pragma unroll
            for (int b = 0; b < SS / 4; ++b) {
                // L2-prefetch batch b+PFD (register-free in-flight depth)
                if (b + PFD < SS / 4) {
                    #pragma unroll
                    for (int r = 0; r < 4; ++r)
                        prefetch_l2(xg + (4 * (b + PFD) + r) * (DD / 4));
                }
                float4 n0, n1, n2, n3;
                float  yn0, yn1, yn2, yn3;
                if (b < SS / 4 - 1) {
                    const int base = (b + 1) * 4;
                    n0 = xg[(base + 0) * (DD / 4)];
                    n1 = xg[(base + 1) * (DD / 4)];
                    n2 = xg[(base + 2) * (DD / 4)];
                    n3 = xg[(base + 3) * (DD / 4)];
                    yn0 = yg[base + 0]; yn1 = yg[base + 1];
                    yn2 = yg[base + 2]; yn3 = yg[base + 3];
                }
                {
                    float4 cc[4] = {c0, c1, c2, c3};
                    float  yy[4] = {yv0, yv1, yv2, yv3};
                    #pragma unroll
                    for (int k = 0; k < 4; ++k) {
                        double2 xd = *reinterpret_cast<double2*>(&cc[k]);
                        float yr = yy[k] - ayv;
                        double yr2 = pack2(yr, yr);
                        double xr_lo = add2(xd.x, na_lo);
                        double xr_hi = add2(xd.y, na_hi);
                        sx_lo  = add2(sx_lo, xr_lo);
                        sx_hi  = add2(sx_hi, xr_hi);
                        sxy_lo = fma2(xr_lo, yr2, sxy_lo);
                        sxy_hi = fma2(xr_hi, yr2, sxy_hi);
                        sxx2   = fma2(xr_lo, xr_lo, sxx2);
                        sxx2   = fma2(xr_hi, xr_hi, sxx2);
                        sy += yr;
                    }
                }
                c0 = n0; c1 = n1; c2 = n2; c3 = n3;
                yv0 = yn0; yv1 = yn1; yv2 = yn2; yv3 = yn3;
            }

            float2 sxxp = unpack2(sxx2);
            float sxx = sxxp.x + sxxp.y;
            float2 sxl = unpack2(sx_lo),  sxh = unpack2(sx_hi);
            float2 syl = unpack2(sxy_lo), syh = unpack2(sxy_hi);
            float tot = sxl.x + sxl.y + sxh.x + sxh.y;

            #pragma unroll
            for (int o = 16; o > 0; o >>= 1) {
                sxx += __shfl_xor_sync(0xFFFFFFFFu, sxx, o);
                tot += __shfl_xor_sync(0xFFFFFFFFu, tot, o);
            }

            const float nD      = (float)(SS * DD);
            const float var     = (sxx - tot * tot / nD) / (nD - 1.0f);
            const float inv_var = 1.0f / var;
            const float c       = sy / (float)SS;
            const float inv_nm1 = 1.0f / (float)(SS - 1);

            float4 rep;
            rep.x = (syl.x - sxl.x * c) * inv_nm1 * inv_var;
            rep.y = (syl.y - sxl.y * c) * inv_nm1 * inv_var;
            rep.z = (syh.x - sxh.x * c) * inv_nm1 * inv_var;
            rep.w = (syh.y - sxh.y * c) * inv_nm1 * inv_var;

            reinterpret_cast<float4*>(out + (size_t)g * DD)[l] = rep;

            // wait for buffer p to be free (first two batches: free by construction)
            if (ib >= 2) bar_sync(BAR_EMPTY(p), 512);

            // pair-interleaved smem store
            {
                const int pp  = w >> 1;
                const int sel = w & 1;
                float* base = reinterpret_cast<float*>(&rep_buf[p][pp][0]);
                base[2 * (4 * l + 0) + sel] = rep.x;
                base[2 * (4 * l + 1) + sel] = rep.y;
                base[2 * (4 * l + 2) + sel] = rep.z;
                base[2 * (4 * l + 3) + sel] = rep.w;
            }
            asm volatile("membar.cta;" ::: "memory");
            bar_arrive(BAR_FULL(p), 512);
        } else {
            // ================= CONSUMER: MLP for batch B =======================
            bar_sync(BAR_FULL(p), 512);      // wait for rep_buf[p]

            // layer 1: thread = hidden unit j (0..255), 4 packed group-pairs
            const int j = tid - 256;
            {
                const float bj = b1[j];
                double acc[GPB / 2];
                #pragma unroll
                for (int pp = 0; pp < GPB / 2; ++pp) acc[pp] = pack2(bj, bj);

                #pragma unroll 4
                for (int d = 0; d < DD; d += 2) {
                    float w0  = W1[(d + 0) * HH + j];
                    float w1v = W1[(d + 1) * HH + j];
                    double wd0 = pack2(w0, w0);
                    double wd1 = pack2(w1v, w1v);
                    #pragma unroll
                    for (int pp = 0; pp < GPB / 2; ++pp) {
                        double2 rp = rep_buf[p][pp][d >> 1];   // broadcast LDS.128
                        acc[pp] = fma2(rp.x, wd0, acc[pp]);
                        acc[pp] = fma2(rp.y, wd1, acc[pp]);
                    }
                }
                #pragma unroll
                for (int pp = 0; pp < GPB / 2; ++pp) {
                    float2 hv = unpack2(acc[pp]);
                    h_s[2 * pp + 0][j] = tanhf(hv.x);
                    h_s[2 * pp + 1][j] = tanhf(hv.y);
                }
            }
            bar_sync(BAR_CONS, 256);         // h_s complete; rep reads drained
            bar_arrive(BAR_EMPTY(p), 512);   // release buffer p to producers

            // layer 2 + heads: one consumer warp per group
            {
                const int w  = wid - 8;
                const int gl = B * GPB + w;

                float acc[KK + 2];
                #pragma unroll
                for (int k = 0; k < KK + 2; ++k) acc[k] = 0.f;

                #pragma unroll
                for (int t = 0; t < HH / 32; ++t) {
                    const int jj = 32 * t + l;
                    const float hv = h_s[w][jj];
                    #pragma unroll
                    for (int k = 0; k < KK + 2; ++k)
                        acc[k] = fmaf(hv, w2t[k][jj], acc[k]);
                }
                #pragma unroll
                for (int k = 0; k < KK + 2; ++k) {
                    #pragma unroll
                    for (int o = 16; o > 0; o >>= 1)
                        acc[k] += __shfl_xor_sync(0xFFFFFFFFu, acc[k], o);
                }

                if (l == 0) {
                    float o0 = acc[0] + b2[0];
                    float o1 = acc[1] + b2[1];
                    float alpha = softplus_f(o0) * (1.0f - EPSV) + EPSV;
                    float beta  = softplus_f(o1) * (1.0f - EPSV) + EPSV;

                    float ok[KK];
                    float m = -INFINITY;
                    #pragma unroll
                    for (int k = 0; k < KK; ++k) {
                        ok[k] = acc[2 + k] + b2[2 + k];
                        m = fmaxf(m, ok[k]);
                    }
                    float s = 0.f;
                    #pragma unroll
                    for (int k = 0; k < KK; ++k) { ok[k] = expf(ok[k] - m); s += ok[k]; }
                    float inv = 1.0f / s;
                    #pragma unroll
                    for (int k = 0; k < KK; ++k)
                        out[OFF_MIX + (size_t)gl * KK + k] = ok[k] * inv;

                    out[OFF_SCALE + gl] = sqrtf(beta / alpha);
                    out[OFF_ALPHA + gl] = alpha;
                    out[OFF_BETA  + gl] = beta;
                }
            }
        }
    }
}

extern "C" void kernel_launch(void* const* d_in, const int* in_sizes, int n_in,
                              void* d_out, int out_size) {
    // inputs (metadata order): index, x, y, anchor_x, anchor_y, W1, b1, W2, b2
    const float* x        = (const float*)d_in[1];
    const float* y        = (const float*)d_in[2];
    const float* anchor_x = (const float*)d_in[3];
    const float* anchor_y = (const float*)d_in[4];
    const float* W1       = (const float*)d_in[5];
    const float* b1       = (const float*)d_in[6];
    const float* W2       = (const float*)d_in[7];
    const float* b2       = (const float*)d_in[8];
    float* out            = (float*)d_out;

    pipeline_kernel<<<GRID, 512>>>(x, y, anchor_x, anchor_y,
                                   W1, b1, W2, b2, out);
}